// round 1
// baseline (speedup 1.0000x reference)
#include <cuda_runtime.h>
#include <cuda_bf16.h>

// Laplacian-pyramid L1 loss, 5 levels, (32,3,512,512) fp32.
// Linearity: pyr(in)-pyr(tg) == pyr(in-tg) -> build ONE pyramid on the diff.

#define BC 96              // batch*channels = 32*3
#define NLVL 5

// per-level full-res side: 512,256,128,64,32 ; down side = half
__device__ float  g_scratch[BC * (256*256 + 128*128 + 64*64 + 32*32 + 16*16)];
__device__ double g_sums[NLVL];

static const int H_LVL[NLVL]   = {512, 256, 128, 64, 32};
static const int OFF_LVL[NLVL] = {
    0,
    BC * 256*256,
    BC * 256*256 + BC * 128*128,
    BC * 256*256 + BC * 128*128 + BC * 64*64,
    BC * 256*256 + BC * 128*128 + BC * 64*64 + BC * 32*32
};

__device__ __forceinline__ int refl(int t, int n) {
    // jnp.pad mode='reflect': -1 -> 1, -2 -> 2, n -> n-2, n+1 -> n-3
    if (t < 0)      return -t;
    if (t >= n)     return 2*n - 2 - t;
    return t;
}

__device__ __forceinline__ float wt(int i) {
    // binomial {1,4,6,4,1}
    return (i == 0 || i == 4) ? 1.0f : ((i == 2) ? 6.0f : 4.0f);
}

__global__ void zero_sums_kernel() {
    if (threadIdx.x < NLVL) g_sums[threadIdx.x] = 0.0;
}

// down[r][c] = (1/256) * sum_{i,j} w_i w_j * d[refl(2r-2+i)][refl(2c-2+j)]
template <bool DIFF>
__global__ void down_kernel(const float* __restrict__ a, const float* __restrict__ b,
                            int srcOff, int dstOff, int H, int total) {
    int idx = blockIdx.x * blockDim.x + threadIdx.x;
    if (idx >= total) return;
    const int W = H, h = H >> 1;
    const int plane = h * h;
    int bc  = idx / plane;
    int rem = idx - bc * plane;
    int r   = rem / h;
    int c   = rem - r * h;

    const float* sa = DIFF ? (a + (size_t)bc * H * W) : (g_scratch + srcOff + (size_t)bc * H * W);
    const float* sb = DIFF ? (b + (size_t)bc * H * W) : nullptr;

    float acc = 0.0f;
#pragma unroll
    for (int i = 0; i < 5; i++) {
        int y = refl(2*r - 2 + i, H);
        const float* rowA = sa + (size_t)y * W;
        const float* rowB = DIFF ? (sb + (size_t)y * W) : nullptr;
        float racc = 0.0f;
#pragma unroll
        for (int j = 0; j < 5; j++) {
            int x = refl(2*c - 2 + j, W);
            float v = DIFF ? (rowA[x] - rowB[x]) : rowA[x];
            racc += wt(j) * v;
        }
        acc += wt(i) * racc;
    }
    g_scratch[dstOff + idx] = acc * (1.0f / 256.0f);
}

// For each pixel of d_l: reconstruct up(y,x) from down_l (zero-stuff conv with
// 4*K -> only parity-matching taps contribute, net weight w_i w_j / 64),
// then accumulate |d - up| into g_sums[lvl].
template <bool DIFF>
__global__ void lap_kernel(const float* __restrict__ a, const float* __restrict__ b,
                           int srcOff, int downOff, int H, int lvl) {
    const int W = H, h = H >> 1;
    const int total = BC * H * W;
    int idx = blockIdx.x * blockDim.x + threadIdx.x;

    float val = 0.0f;
    if (idx < total) {
        const int plane = H * W;
        int bc  = idx / plane;
        int rem = idx - bc * plane;
        int y   = rem / W;
        int x   = rem - y * W;

        float dval = DIFF ? (a[idx] - b[idx]) : g_scratch[srcOff + idx];

        const float* dn = g_scratch + downOff + (size_t)bc * h * h;
        float acc = 0.0f;
#pragma unroll
        for (int i = 0; i < 5; i++) {
            if (((i ^ y) & 1) != 0) continue;          // stuffed zeros: parity must match
            int ty = refl(y - 2 + i, H);
            int ry = ty >> 1;
            const float* drow = dn + (size_t)ry * h;
            float racc = 0.0f;
#pragma unroll
            for (int j = 0; j < 5; j++) {
                if (((j ^ x) & 1) != 0) continue;
                int tx = refl(x - 2 + j, W);
                racc += wt(j) * drow[tx >> 1];
            }
            acc += wt(i) * racc;
        }
        float up = acc * (1.0f / 64.0f);
        val = fabsf(dval - up);
    }

    // block reduction
    __shared__ float sdata[256];
    int t = threadIdx.x;
    sdata[t] = val;
    __syncthreads();
#pragma unroll
    for (int s = 128; s > 0; s >>= 1) {
        if (t < s) sdata[t] += sdata[t + s];
        __syncthreads();
    }
    if (t == 0) atomicAdd(&g_sums[lvl], (double)sdata[0]);
}

__global__ void finalize_kernel(float* out) {
    if (threadIdx.x == 0 && blockIdx.x == 0) {
        double tot = 0.0;
        const int hs[NLVL] = {512, 256, 128, 64, 32};
#pragma unroll
        for (int l = 0; l < NLVL; l++) {
            double numel = (double)BC * hs[l] * hs[l];
            tot += g_sums[l] / numel;
        }
        out[0] = (float)tot;
    }
}

extern "C" void kernel_launch(void* const* d_in, const int* in_sizes, int n_in,
                              void* d_out, int out_size) {
    const float* input  = (const float*)d_in[0];
    const float* target = (const float*)d_in[1];
    float* out = (float*)d_out;

    zero_sums_kernel<<<1, 32>>>();

    const int TB = 256;

    // Level 0: diff computed on the fly
    {
        int H = H_LVL[0], h = H >> 1;
        int totDown = BC * h * h;
        down_kernel<true><<<(totDown + TB - 1) / TB, TB>>>(input, target, 0, OFF_LVL[0], H, totDown);
        int totLap = BC * H * H;
        lap_kernel<true><<<(totLap + TB - 1) / TB, TB>>>(input, target, 0, OFF_LVL[0], H, 0);
    }
    // Levels 1..4: source is previous down buffer
    for (int l = 1; l < NLVL; l++) {
        int H = H_LVL[l], h = H >> 1;
        int srcOff = OFF_LVL[l - 1];
        int dstOff = OFF_LVL[l];
        int totDown = BC * h * h;
        down_kernel<false><<<(totDown + TB - 1) / TB, TB>>>(nullptr, nullptr, srcOff, dstOff, H, totDown);
        int totLap = BC * H * H;
        lap_kernel<false><<<(totLap + TB - 1) / TB, TB>>>(nullptr, nullptr, srcOff, dstOff, H, l);
    }

    finalize_kernel<<<1, 32>>>(out);
}

// round 2
// speedup vs baseline: 1.3537x; 1.3537x over previous
#include <cuda_runtime.h>
#include <cuda_bf16.h>

// Laplacian-pyramid L1 loss, 5 levels, (32,3,512,512) fp32.
// Linearity: pyr(in)-pyr(tg) == pyr(in-tg) -> ONE pyramid on the diff.
// Fully fused per level: tile load -> separable gauss+down (smem) -> write down
// -> upsample+|.| reduce, all in one kernel.

#define BC 96
#define NLVL 5

__device__ float  g_scratch[BC * (256*256 + 128*128 + 64*64 + 32*32 + 16*16)];
__device__ double g_sums[NLVL];

__device__ __forceinline__ int refl(int t, int n) {
    if (t < 0)  return -t;
    if (t >= n) return 2*n - 2 - t;
    return t;
}
__device__ __forceinline__ float wt(int i) {
    return (i == 0 || i == 4) ? 1.0f : ((i == 2) ? 6.0f : 4.0f);
}

__global__ void zero_sums_kernel() {
    if (threadIdx.x < NLVL) g_sums[threadIdx.x] = 0.0;
}

// One block = one TILE x TILE full-res region of one bc-plane.
// DIFF: compute d = a - b on the fly (level 0); else read scratch.
template <int TILE, bool DIFF>
__global__ void lvl_kernel(const float* __restrict__ a, const float* __restrict__ b,
                           int srcOff, int dstOff, int H, int lvl, int tilesRow)
{
    constexpr int DT = TILE + 8;       // d tile side (4-halo each side)
    constexpr int HT = TILE/2 + 2;     // down tile side (1-halo each side)
    constexpr int HI = TILE/2;         // down interior

    __shared__ float sd [DT * DT];
    __shared__ float st [DT * HT];     // horizontal-pass temp
    __shared__ float sdn[HT * HT];
    __shared__ float sred[8];

    const int W = H, h = H >> 1;
    const int tid = threadIdx.x;
    const int ty = blockIdx.x / tilesRow, tx = blockIdx.x - ty * tilesRow;
    const int bc = blockIdx.y;
    const int y0 = ty * TILE, x0 = tx * TILE;
    const int r0 = y0 >> 1,  c0 = x0 >> 1;

    const float* sa = DIFF ? a + (size_t)bc * H * W
                           : g_scratch + srcOff + (size_t)bc * H * W;
    const float* sb = DIFF ? b + (size_t)bc * H * W : nullptr;

    // ---- load d tile with reflect padding ----
    for (int idx = tid; idx < DT * DT; idx += blockDim.x) {
        int ly = idx / DT, lx = idx - ly * DT;
        int gy = refl(y0 - 4 + ly, H);
        int gx = refl(x0 - 4 + lx, W);
        float v = sa[(size_t)gy * W + gx];
        if (DIFF) v -= sb[(size_t)gy * W + gx];
        sd[idx] = v;
    }
    __syncthreads();

    // ---- horizontal pass, stride 2: st[ly][dc] = sum_j w_j * sd[ly][2dc+j] ----
    for (int idx = tid; idx < DT * HT; idx += blockDim.x) {
        int ly = idx / HT, dc = idx - ly * HT;
        const float* row = sd + ly * DT + 2 * dc;
        st[idx] = row[0] + 4.f*row[1] + 6.f*row[2] + 4.f*row[3] + row[4];
    }
    __syncthreads();

    // ---- vertical pass, stride 2: sdn[dr][dc] ----
    for (int idx = tid; idx < HT * HT; idx += blockDim.x) {
        int dr = idx / HT, dc = idx - dr * HT;
        const float* col = st + (2 * dr) * HT + dc;
        sdn[idx] = (col[0] + 4.f*col[HT] + 6.f*col[2*HT] + 4.f*col[3*HT] + col[4*HT])
                   * (1.0f / 256.0f);
    }
    __syncthreads();

    // ---- write interior down tile to scratch (next level's source) ----
    {
        float* gdn = g_scratch + dstOff + (size_t)bc * h * h;
        for (int idx = tid; idx < HI * HI; idx += blockDim.x) {
            int dr = idx / HI, dc = idx - dr * HI;
            gdn[(size_t)(r0 + dr) * h + (c0 + dc)] = sdn[(dr + 1) * HT + (dc + 1)];
        }
    }

    // ---- upsample from sdn, accumulate |d - up| ----
    float lsum = 0.0f;
    for (int idx = tid; idx < TILE * TILE; idx += blockDim.x) {
        int py = idx / TILE, px = idx - py * TILE;
        int y = y0 + py, x = x0 + px;
        float dval = sd[(py + 4) * DT + (px + 4)];
        float acc = 0.0f;
#pragma unroll
        for (int i = 0; i < 5; i++) {
            if (((i ^ y) & 1) != 0) continue;      // zero-stuffed rows
            int t  = refl(y - 2 + i, H);
            int dr = (t >> 1) - r0 + 1;
            const float* drow = sdn + dr * HT;
            float racc = 0.0f;
#pragma unroll
            for (int j = 0; j < 5; j++) {
                if (((j ^ x) & 1) != 0) continue;  // zero-stuffed cols
                int u = refl(x - 2 + j, W);
                racc += wt(j) * drow[(u >> 1) - c0 + 1];
            }
            acc += wt(i) * racc;
        }
        lsum += fabsf(dval - acc * (1.0f / 64.0f));
    }

    // ---- block reduce -> one atomic per block ----
#pragma unroll
    for (int o = 16; o; o >>= 1) lsum += __shfl_down_sync(0xffffffffu, lsum, o);
    if ((tid & 31) == 0) sred[tid >> 5] = lsum;
    __syncthreads();
    if (tid < 8) {
        float v = sred[tid];
#pragma unroll
        for (int o = 4; o; o >>= 1) v += __shfl_down_sync(0xffu, v, o);
        if (tid == 0) atomicAdd(&g_sums[lvl], (double)v);
    }
}

__global__ void finalize_kernel(float* out) {
    if (threadIdx.x == 0 && blockIdx.x == 0) {
        double tot = 0.0;
        const int hs[NLVL] = {512, 256, 128, 64, 32};
#pragma unroll
        for (int l = 0; l < NLVL; l++) {
            double numel = (double)BC * hs[l] * hs[l];
            tot += g_sums[l] / numel;
        }
        out[0] = (float)tot;
    }
}

extern "C" void kernel_launch(void* const* d_in, const int* in_sizes, int n_in,
                              void* d_out, int out_size) {
    const float* input  = (const float*)d_in[0];
    const float* target = (const float*)d_in[1];
    float* out = (float*)d_out;

    static const int OFF[NLVL] = {
        0,
        BC * 256*256,
        BC * 256*256 + BC * 128*128,
        BC * 256*256 + BC * 128*128 + BC * 64*64,
        BC * 256*256 + BC * 128*128 + BC * 64*64 + BC * 32*32
    };

    zero_sums_kernel<<<1, 32>>>();

    const int TB = 256;

    // L0: H=512, 8x8 tiles of 64
    lvl_kernel<64, true ><<<dim3(8*8, BC), TB>>>(input, target, 0,      OFF[0], 512, 0, 8);
    // L1: H=256, 4x4
    lvl_kernel<64, false><<<dim3(4*4, BC), TB>>>(nullptr, nullptr, OFF[0], OFF[1], 256, 1, 4);
    // L2: H=128, 2x2
    lvl_kernel<64, false><<<dim3(2*2, BC), TB>>>(nullptr, nullptr, OFF[1], OFF[2], 128, 2, 2);
    // L3: H=64, 1x1
    lvl_kernel<64, false><<<dim3(1,   BC), TB>>>(nullptr, nullptr, OFF[2], OFF[3],  64, 3, 1);
    // L4: H=32, tile 32
    lvl_kernel<32, false><<<dim3(1,   BC), TB>>>(nullptr, nullptr, OFF[3], OFF[4],  32, 4, 1);

    finalize_kernel<<<1, 32>>>(out);
}

// round 3
// speedup vs baseline: 3.4242x; 2.5295x over previous
#include <cuda_runtime.h>
#include <cuda_bf16.h>

// Laplacian-pyramid L1 loss, 5 levels, (32,3,512,512) fp32.
// pyr(in)-pyr(tg) == pyr(in-tg). Reflect padding is scale-consistent:
// down[-1]==down[1], down[h]==down[h-1]  ==>  upsample needs no refl logic,
// just a 1-halo'd down tile and (1,6,1)/(4,4) parity taps. Fully separable.

#define BC 96
#define NLVL 5

__device__ float  g_scratch[BC * (256*256 + 128*128 + 64*64)];
__device__ double g_sums[NLVL];

__device__ __forceinline__ int refl(int t, int n) {
    if (t < 0)  return -t;
    if (t >= n) return 2*n - 2 - t;
    return t;
}
__device__ __forceinline__ float wt(int i) {
    return (i == 0 || i == 4) ? 1.0f : ((i == 2) ? 6.0f : 4.0f);
}

__global__ void zero_sums_kernel() {
    if (threadIdx.x < NLVL) g_sums[threadIdx.x] = 0.0;
}

__device__ __forceinline__ void block_reduce_atomic(float v, int lvl, float* sred) {
    const int tid = threadIdx.x;
#pragma unroll
    for (int o = 16; o; o >>= 1) v += __shfl_down_sync(0xffffffffu, v, o);
    if ((tid & 31) == 0) sred[tid >> 5] = v;
    __syncthreads();
    if (tid < 16) {
        float x = sred[tid];
#pragma unroll
        for (int o = 8; o; o >>= 1) x += __shfl_down_sync(0xffffu, x, o);
        if (tid == 0) atomicAdd(&g_sums[lvl], (double)x);
    }
    __syncthreads();
}

// ---------------- tiled kernel: levels 0..2 ----------------
// One block = TILE x TILE region of one bc-plane. 512 threads.
template <int TILE, bool DIFF>
__global__ __launch_bounds__(512)
void lvl_kernel(const float* __restrict__ a, const float* __restrict__ b,
                int srcOff, int dstOff, int H, int lvl, int tilesRow)
{
    constexpr int DT = TILE + 8;     // full-res tile + 4-halo
    constexpr int HT = TILE/2 + 2;   // down tile + 1-halo
    constexpr int HI = TILE/2;

    __shared__ float sd [DT * DT];
    __shared__ float st [DT * HT];   // horiz-gauss temp; aliased later as sup[HT*TILE]
    __shared__ float sdn[HT * HT];
    __shared__ float sred[16];

    const int W = H, h = H >> 1;
    const int tid = threadIdx.x;
    const int NT  = blockDim.x;
    const int ty = blockIdx.x / tilesRow, tx = blockIdx.x - ty * tilesRow;
    const int bc = blockIdx.y;
    const int y0 = ty * TILE, x0 = tx * TILE;
    const int r0 = y0 >> 1,  c0 = x0 >> 1;

    const float* sa = DIFF ? a + (size_t)bc * H * W
                           : g_scratch + srcOff + (size_t)bc * H * W;
    const float* sb = DIFF ? b + (size_t)bc * H * W : nullptr;

    // load diff tile (reflect)
    for (int idx = tid; idx < DT * DT; idx += NT) {
        int ly = idx / DT, lx = idx - ly * DT;
        int gy = refl(y0 - 4 + ly, H);
        int gx = refl(x0 - 4 + lx, W);
        size_t g = (size_t)gy * W + gx;
        float v = sa[g];
        if (DIFF) v -= sb[g];
        sd[idx] = v;
    }
    __syncthreads();

    // horizontal gauss, stride 2 (no refl: 4-halo covers)
    for (int idx = tid; idx < DT * HT; idx += NT) {
        int ly = idx / HT, dc = idx - ly * HT;
        const float* r = sd + ly * DT + 2 * dc;
        st[idx] = r[0] + 4.f*r[1] + 6.f*r[2] + 4.f*r[3] + r[4];
    }
    __syncthreads();

    // vertical gauss, stride 2
    for (int idx = tid; idx < HT * HT; idx += NT) {
        int dr = idx / HT, dc = idx - dr * HT;
        const float* c = st + (2 * dr) * HT + dc;
        sdn[idx] = (c[0] + 4.f*c[HT] + 6.f*c[2*HT] + 4.f*c[3*HT] + c[4*HT]) * (1.f/256.f);
    }
    __syncthreads();

    // write interior down tile (next level source)
    {
        float* gdn = g_scratch + dstOff + (size_t)bc * h * h;
        for (int idx = tid; idx < HI * HI; idx += NT) {
            int dr = idx / HI, dc = idx - dr * HI;
            gdn[(size_t)(r0 + dr) * h + (c0 + dc)] = sdn[(dr + 1) * HT + (dc + 1)];
        }
    }

    // horizontal upsample into sup (alias st; st is dead, sync above guards)
    float* sup = st;
    for (int idx = tid; idx < HT * TILE; idx += NT) {
        int dr = idx / TILE, px = idx - dr * TILE;
        const float* dnr = sdn + dr * HT;
        int lc = (px >> 1) + 1;
        sup[idx] = (px & 1) ? 4.f * (dnr[lc] + dnr[lc + 1])
                            : dnr[lc - 1] + 6.f * dnr[lc] + dnr[lc + 1];
    }
    __syncthreads();

    // vertical upsample + |d - up|
    float lsum = 0.0f;
    for (int idx = tid; idx < TILE * TILE; idx += NT) {
        int py = idx / TILE, px = idx - py * TILE;
        int lr = (py >> 1) + 1;
        float u = (py & 1) ? 4.f * (sup[lr*TILE + px] + sup[(lr+1)*TILE + px])
                           : sup[(lr-1)*TILE + px] + 6.f*sup[lr*TILE + px] + sup[(lr+1)*TILE + px];
        float dval = sd[(py + 4) * DT + (px + 4)];
        lsum += fabsf(dval - u * (1.f/64.f));
    }
    block_reduce_atomic(lsum, lvl, sred);
}

// ---------------- in-smem level step (whole plane resident) ----------------
__device__ __forceinline__ void level_smem(const float* src, int sStride, int H,
                                           float* st, float* sdn,
                                           float& lsum, int tid, int NT)
{
    const int h = H >> 1, HT2 = h + 2;
    // horizontal gauss (global down col dc-1), reflect via full plane
    for (int idx = tid; idx < H * HT2; idx += NT) {
        int y = idx / HT2, dc = idx - y * HT2;
        const float* row = src + y * sStride;
        float acc = 0.f;
#pragma unroll
        for (int j = 0; j < 5; j++) acc += wt(j) * row[refl(2*dc - 4 + j, H)];
        st[idx] = acc;
    }
    __syncthreads();
    for (int idx = tid; idx < HT2 * HT2; idx += NT) {
        int dr = idx / HT2, dc = idx - dr * HT2;
        float acc = 0.f;
#pragma unroll
        for (int i = 0; i < 5; i++) acc += wt(i) * st[refl(2*dr - 4 + i, H) * HT2 + dc];
        sdn[idx] = acc * (1.f/256.f);
    }
    __syncthreads();
    float* sup = st;  // alias (same size H*HT2)
    for (int idx = tid; idx < HT2 * H; idx += NT) {
        int dr = idx / H, x = idx - dr * H;
        const float* dnr = sdn + dr * HT2;
        int lc = (x >> 1) + 1;
        sup[idx] = (x & 1) ? 4.f * (dnr[lc] + dnr[lc + 1])
                           : dnr[lc - 1] + 6.f * dnr[lc] + dnr[lc + 1];
    }
    __syncthreads();
    for (int idx = tid; idx < H * H; idx += NT) {
        int y = idx / H, x = idx - y * H;
        int lr = (y >> 1) + 1;
        float u = (y & 1) ? 4.f * (sup[lr*H + x] + sup[(lr+1)*H + x])
                          : sup[(lr-1)*H + x] + 6.f*sup[lr*H + x] + sup[(lr+1)*H + x];
        lsum += fabsf(src[y * sStride + x] - u * (1.f/64.f));
    }
    __syncthreads();
}

// ---------------- fused levels 3+4: one block per bc-plane ----------------
__global__ __launch_bounds__(512)
void tail_kernel(int srcOff)
{
    __shared__ float sa  [64 * 64];     // level-3 source plane
    __shared__ float st3 [64 * 34];     // horiz temp / sup (aliased)
    __shared__ float sdn3[34 * 34];     // level-3 down (+halo) -> level-4 source
    __shared__ float st4 [32 * 18];
    __shared__ float sdn4[18 * 18];
    __shared__ float sred[16];

    const int tid = threadIdx.x, NT = blockDim.x;
    const int bc = blockIdx.x;

    const float* g = g_scratch + srcOff + (size_t)bc * 64 * 64;
    for (int idx = tid; idx < 64 * 64; idx += NT) sa[idx] = g[idx];
    __syncthreads();

    float l3 = 0.f, l4 = 0.f;
    level_smem(sa, 64, 64, st3, sdn3, l3, tid, NT);
    block_reduce_atomic(l3, 3, sred);
    // level-4 source = interior of sdn3 (stride 34, offset (1,1))
    level_smem(sdn3 + 34 + 1, 34, 32, st4, sdn4, l4, tid, NT);
    block_reduce_atomic(l4, 4, sred);
}

__global__ void finalize_kernel(float* out) {
    if (threadIdx.x == 0 && blockIdx.x == 0) {
        double tot = 0.0;
        const int hs[NLVL] = {512, 256, 128, 64, 32};
#pragma unroll
        for (int l = 0; l < NLVL; l++) {
            double numel = (double)BC * hs[l] * hs[l];
            tot += g_sums[l] / numel;
        }
        out[0] = (float)tot;
    }
}

extern "C" void kernel_launch(void* const* d_in, const int* in_sizes, int n_in,
                              void* d_out, int out_size) {
    const float* input  = (const float*)d_in[0];
    const float* target = (const float*)d_in[1];
    float* out = (float*)d_out;

    const int OFF0 = 0;
    const int OFF1 = BC * 256*256;
    const int OFF2 = BC * 256*256 + BC * 128*128;

    zero_sums_kernel<<<1, 32>>>();

    lvl_kernel<64, true ><<<dim3(64, BC), 512>>>(input,  target,  0,    OFF0, 512, 0, 8);
    lvl_kernel<64, false><<<dim3(16, BC), 512>>>(nullptr, nullptr, OFF0, OFF1, 256, 1, 4);
    lvl_kernel<64, false><<<dim3(4,  BC), 512>>>(nullptr, nullptr, OFF1, OFF2, 128, 2, 2);
    tail_kernel<<<BC, 512>>>(OFF2);

    finalize_kernel<<<1, 32>>>(out);
}